// round 14
// baseline (speedup 1.0000x reference)
#include <cuda_runtime.h>
#include <cuda_fp16.h>
#include <cstdint>

#define N_MAX   100000
#define E_MAX   800000
#define HD      128
#define NHEADS  8

// Scratch (__device__ globals per allocation rules)
__device__ __half g_Qh[N_MAX * HD];    // Q fp16 (score-path only, like K)
__device__ __half g_KV[N_MAX * 256];   // per node: 32 groups of {K[4],V[4]} fp16
__device__ int    g_cnt[N_MAX];
__device__ int    g_off[N_MAX + 1];
__device__ int    g_pos[N_MAX];
__device__ int    g_srcs[E_MAX];
__device__ int    g_bsum[256];

// ---------------------------------------------------------------------------
// tf32 helpers
// ---------------------------------------------------------------------------
__device__ __forceinline__ float tf32_rna(float x) {
    float r;
    asm("cvt.rna.tf32.f32 %0, %1;" : "=f"(r) : "f"(x));
    return r;
}
__device__ __forceinline__ void mma_tf32(float c[4],
                                         uint32_t a0, uint32_t a1, uint32_t a2, uint32_t a3,
                                         uint32_t b0, uint32_t b1) {
    asm volatile(
        "mma.sync.aligned.m16n8k8.row.col.f32.tf32.tf32.f32 "
        "{%0,%1,%2,%3}, {%4,%5,%6,%7}, {%8,%9}, {%0,%1,%2,%3};"
        : "+f"(c[0]), "+f"(c[1]), "+f"(c[2]), "+f"(c[3])
        : "r"(a0), "r"(a1), "r"(a2), "r"(a3), "r"(b0), "r"(b1));
}

// ---------------------------------------------------------------------------
// QKV GEMM (exact R12 config — confirmed local optimum).
// Block 64x128, 8 warps (2 warpM x 4 warpN), warp tile 32x32, K in 4x32 chunks.
// blockIdx.y: 0 = Q -> g_Qh fp16; 1 = K -> g_KV slot 0; 2 = V -> g_KV slot 4.
// ---------------------------------------------------------------------------
#define QKSX 36
#define QKSW 136

__global__ void __launch_bounds__(256)
qkv_gemm_tc(const float* __restrict__ x,
            const float* __restrict__ Wq, const float* __restrict__ bq,
            const float* __restrict__ Wk, const float* __restrict__ bk,
            const float* __restrict__ Wv, const float* __restrict__ bv,
            int n)
{
    const int mode = blockIdx.y;           // 0=Q 1=K 2=V
    const float* W; const float* bias;
    if (mode == 0)      { W = Wq; bias = bq; }
    else if (mode == 1) { W = Wk; bias = bk; }
    else                { W = Wv; bias = bv; }

    extern __shared__ float smemf[];
    float* xs = smemf;                 // [64][QKSX]
    float* ws = smemf + 64 * QKSX;     // [32][QKSW]

    const int tid   = threadIdx.x;
    const int lane  = tid & 31;
    const int wid   = tid >> 5;
    const int warpM = wid >> 2;
    const int warpN = wid & 3;
    const int g     = lane >> 2;
    const int tg    = lane & 3;
    const int row0  = blockIdx.x * 64;

    float acc[2][4][4];
    #pragma unroll
    for (int mt = 0; mt < 2; mt++)
        #pragma unroll
        for (int nt = 0; nt < 4; nt++)
            #pragma unroll
            for (int i = 0; i < 4; i++) acc[mt][nt][i] = 0.f;

    #pragma unroll
    for (int kc = 0; kc < 128; kc += 32) {
        #pragma unroll
        for (int j = 0; j < 2; j++) {
            int idx = tid + j * 256;
            int r   = idx >> 3;
            int k4  = (idx & 7) * 4;
            float4 v = make_float4(0.f, 0.f, 0.f, 0.f);
            int gr = row0 + r;
            if (gr < n) v = *(const float4*)&x[(size_t)gr * 128 + kc + k4];
            float* p = &xs[r * QKSX + k4];
            p[0] = tf32_rna(v.x);
            p[1] = tf32_rna(v.y);
            p[2] = tf32_rna(v.z);
            p[3] = tf32_rna(v.w);
        }
        #pragma unroll
        for (int j = 0; j < 4; j++) {
            int idx = tid + j * 256;
            int kk  = idx >> 5;
            int n4  = (idx & 31) * 4;
            float4 v = *(const float4*)&W[(size_t)(kc + kk) * 128 + n4];
            float* p = &ws[kk * QKSW + n4];
            p[0] = tf32_rna(v.x);
            p[1] = tf32_rna(v.y);
            p[2] = tf32_rna(v.z);
            p[3] = tf32_rna(v.w);
        }
        __syncthreads();

        #pragma unroll
        for (int k8 = 0; k8 < 4; k8++) {
            const int kb = k8 * 8;
            float af[2][4];
            #pragma unroll
            for (int mt = 0; mt < 2; mt++) {
                int r = warpM * 32 + mt * 16 + g;
                af[mt][0] = xs[r * QKSX + kb + tg];
                af[mt][1] = xs[(r + 8) * QKSX + kb + tg];
                af[mt][2] = xs[r * QKSX + kb + tg + 4];
                af[mt][3] = xs[(r + 8) * QKSX + kb + tg + 4];
            }
            float bfr[4][2];
            #pragma unroll
            for (int nt = 0; nt < 4; nt++) {
                int c = warpN * 32 + nt * 8 + g;
                bfr[nt][0] = ws[(kb + tg) * QKSW + c];
                bfr[nt][1] = ws[(kb + tg + 4) * QKSW + c];
            }
            #pragma unroll
            for (int mt = 0; mt < 2; mt++) {
                #pragma unroll
                for (int nt = 0; nt < 4; nt++) {
                    mma_tf32(acc[mt][nt],
                             __float_as_uint(af[mt][0]), __float_as_uint(af[mt][1]),
                             __float_as_uint(af[mt][2]), __float_as_uint(af[mt][3]),
                             __float_as_uint(bfr[nt][0]), __float_as_uint(bfr[nt][1]));
                }
            }
        }
        __syncthreads();
    }

    #pragma unroll
    for (int nt = 0; nt < 4; nt++) {
        int col = warpN * 32 + nt * 8 + tg * 2;
        float b0 = __ldg(&bias[col]);
        float b1 = __ldg(&bias[col + 1]);
        int grp = col >> 2;
        int off = col & 3;
        int kvslot = (mode == 1) ? 0 : 4;
        #pragma unroll
        for (int mt = 0; mt < 2; mt++) {
            #pragma unroll
            for (int half = 0; half < 2; half++) {
                int r = row0 + warpM * 32 + mt * 16 + g + half * 8;
                if (r >= n) continue;
                float o0 = acc[mt][nt][half * 2 + 0] + b0;
                float o1 = acc[mt][nt][half * 2 + 1] + b1;
                __half2 h = __float22half2_rn(make_float2(o0, o1));
                if (mode == 0) {
                    *(__half2*)&g_Qh[(size_t)r * 128 + col] = h;
                } else {
                    size_t hidx = (size_t)r * 256 + grp * 8 + kvslot + off;
                    *(__half2*)&g_KV[hidx] = h;
                }
            }
        }
    }
}

// ---------------------------------------------------------------------------
// Counting sort of edges by dst
// ---------------------------------------------------------------------------
__global__ void zero_cnt(int n)
{
    int i = blockIdx.x * blockDim.x + threadIdx.x;
    if (i < n) g_cnt[i] = 0;
}

__global__ void hist_kernel(const int* __restrict__ ei, int E)
{
    int i = blockIdx.x * blockDim.x + threadIdx.x;
    if (i < E) atomicAdd(&g_cnt[ei[E + i]], 1);
}

__global__ void scan_pass1(int n)
{
    __shared__ int s[256];
    int b   = blockIdx.x;
    int t   = threadIdx.x;
    int idx = b * 1024 + t * 4;
    int sum = 0;
    #pragma unroll
    for (int k = 0; k < 4; k++)
        if (idx + k < n) sum += g_cnt[idx + k];
    s[t] = sum;
    __syncthreads();
    for (int o = 128; o > 0; o >>= 1) {
        if (t < o) s[t] += s[t + o];
        __syncthreads();
    }
    if (t == 0) g_bsum[b] = s[0];
}

__global__ void scan_pass2(int nb)
{
    __shared__ int s[256];
    int t = threadIdx.x;
    s[t] = (t < nb) ? g_bsum[t] : 0;
    __syncthreads();
    #pragma unroll
    for (int o = 1; o < 256; o <<= 1) {
        int add = (t >= o) ? s[t - o] : 0;
        __syncthreads();
        s[t] += add;
        __syncthreads();
    }
    if (t < nb) g_bsum[t] = (t == 0) ? 0 : s[t - 1];
}

__global__ void scan_pass3(int n, int E)
{
    __shared__ int s[256];
    int b   = blockIdx.x;
    int t   = threadIdx.x;
    int idx = b * 1024 + t * 4;
    int v[4];
    int sum = 0;
    #pragma unroll
    for (int k = 0; k < 4; k++) {
        v[k] = (idx + k < n) ? g_cnt[idx + k] : 0;
        sum += v[k];
    }
    s[t] = sum;
    __syncthreads();
    #pragma unroll
    for (int o = 1; o < 256; o <<= 1) {
        int add = (t >= o) ? s[t - o] : 0;
        __syncthreads();
        s[t] += add;
        __syncthreads();
    }
    int base = g_bsum[b] + s[t] - sum;
    #pragma unroll
    for (int k = 0; k < 4; k++) {
        if (idx + k < n) {
            g_off[idx + k] = base;
            g_pos[idx + k] = base;
        }
        base += v[k];
    }
    if (b == 0 && t == 0) g_off[n] = E;
}

__global__ void scatter_kernel(const int* __restrict__ ei, int E)
{
    int i = blockIdx.x * blockDim.x + threadIdx.x;
    if (i >= E) return;
    int src = ei[i];
    int dst = ei[E + i];
    int p = atomicAdd(&g_pos[dst], 1);
    g_srcs[p] = src;
}

// ---------------------------------------------------------------------------
// Segmented gather: 1 warp per TWO nodes, chunks interleaved -> two
// independent load chains per warp (cross-node MLP, zero extra traffic).
// All guards warp-uniform; full-mask shfl safe.
// ---------------------------------------------------------------------------
__device__ __forceinline__ void gather_edge(uint4 pk, float4 q,
                                            float& ax, float& ay, float& az,
                                            float& aw, float& z)
{
    float2 k0 = __half22float2(*(__half2*)&pk.x);
    float2 k1 = __half22float2(*(__half2*)&pk.y);
    float2 v0 = __half22float2(*(__half2*)&pk.z);
    float2 v1 = __half22float2(*(__half2*)&pk.w);

    float dot = k0.x * q.x + k0.y * q.y + k1.x * q.z + k1.y * q.w;
    dot += __shfl_xor_sync(0xffffffffu, dot, 1);
    dot += __shfl_xor_sync(0xffffffffu, dot, 2);
    dot *= 0.25f;
    dot = fminf(fmaxf(dot, -5.0f), 5.0f);
    float score = __expf(dot);

    ax += score * v0.x;
    ay += score * v0.y;
    az += score * v1.x;
    aw += score * v1.y;
    z  += score;
}

__device__ __forceinline__ float4 load_q(int node, int lane)
{
    uint2 qp = *(const uint2*)&g_Qh[(size_t)node * 128 + lane * 4];
    float2 q0 = __half22float2(*(__half2*)&qp.x);
    float2 q1 = __half22float2(*(__half2*)&qp.y);
    return make_float4(q0.x, q0.y, q1.x, q1.y);
}

__global__ void __launch_bounds__(256)
gather_kernel(float* __restrict__ out, int n)
{
    int pair = (blockIdx.x * blockDim.x + threadIdx.x) >> 5;
    int lane = threadIdx.x & 31;
    int nodeA = pair * 2;
    int nodeB = pair * 2 + 1;
    if (nodeA >= n) return;
    bool hasB = (nodeB < n);

    int begA = g_off[nodeA], endA = g_off[nodeA + 1];
    int begB = 0, endB = 0;
    if (hasB) { begB = g_off[nodeB]; endB = g_off[nodeB + 1]; }

    float4 qA = load_q(nodeA, lane);
    float4 qB = hasB ? load_q(nodeB, lane) : make_float4(0.f, 0.f, 0.f, 0.f);

    float axA = 0.f, ayA = 0.f, azA = 0.f, awA = 0.f, zA = 0.f;
    float axB = 0.f, ayB = 0.f, azB = 0.f, awB = 0.f, zB = 0.f;

    int jA = begA, jB = begB;
    int lastA = endA - 1, lastB = endB - 1;

    while (jA < endA || jB < endB) {
        bool aA = jA < endA;
        bool aB = jB < endB;

        int sA0 = 0, sA1 = 0, sA2 = 0, sA3 = 0;
        int sB0 = 0, sB1 = 0, sB2 = 0, sB3 = 0;
        if (aA) {
            sA0 = __ldg(&g_srcs[jA]);
            sA1 = __ldg(&g_srcs[min(jA + 1, lastA)]);
            sA2 = __ldg(&g_srcs[min(jA + 2, lastA)]);
            sA3 = __ldg(&g_srcs[min(jA + 3, lastA)]);
        }
        if (aB) {
            sB0 = __ldg(&g_srcs[jB]);
            sB1 = __ldg(&g_srcs[min(jB + 1, lastB)]);
            sB2 = __ldg(&g_srcs[min(jB + 2, lastB)]);
            sB3 = __ldg(&g_srcs[min(jB + 3, lastB)]);
        }

        uint4 pA0, pA1, pA2, pA3, pB0, pB1, pB2, pB3;
        if (aA) {
            pA0 = *(const uint4*)&g_KV[(size_t)sA0 * 256 + lane * 8];
            pA1 = *(const uint4*)&g_KV[(size_t)sA1 * 256 + lane * 8];
            pA2 = *(const uint4*)&g_KV[(size_t)sA2 * 256 + lane * 8];
            pA3 = *(const uint4*)&g_KV[(size_t)sA3 * 256 + lane * 8];
        }
        if (aB) {
            pB0 = *(const uint4*)&g_KV[(size_t)sB0 * 256 + lane * 8];
            pB1 = *(const uint4*)&g_KV[(size_t)sB1 * 256 + lane * 8];
            pB2 = *(const uint4*)&g_KV[(size_t)sB2 * 256 + lane * 8];
            pB3 = *(const uint4*)&g_KV[(size_t)sB3 * 256 + lane * 8];
        }

        if (aA) {
            gather_edge(pA0, qA, axA, ayA, azA, awA, zA);
            if (jA + 1 < endA) gather_edge(pA1, qA, axA, ayA, azA, awA, zA);
            if (jA + 2 < endA) gather_edge(pA2, qA, axA, ayA, azA, awA, zA);
            if (jA + 3 < endA) gather_edge(pA3, qA, axA, ayA, azA, awA, zA);
            jA += 4;
        }
        if (aB) {
            gather_edge(pB0, qB, axB, ayB, azB, awB, zB);
            if (jB + 1 < endB) gather_edge(pB1, qB, axB, ayB, azB, awB, zB);
            if (jB + 2 < endB) gather_edge(pB2, qB, axB, ayB, azB, awB, zB);
            if (jB + 3 < endB) gather_edge(pB3, qB, axB, ayB, azB, awB, zB);
            jB += 4;
        }
    }

    float sA = 1.0f / (zA + 1e-6f);
    *(float4*)&out[(size_t)nodeA * 128 + lane * 4] =
        make_float4(axA * sA, ayA * sA, azA * sA, awA * sA);
    if (hasB) {
        float sB = 1.0f / (zB + 1e-6f);
        *(float4*)&out[(size_t)nodeB * 128 + lane * 4] =
            make_float4(axB * sB, ayB * sB, azB * sB, awB * sB);
    }
}

// ---------------------------------------------------------------------------
extern "C" void kernel_launch(void* const* d_in, const int* in_sizes, int n_in,
                              void* d_out, int out_size)
{
    const float* x  = (const float*)d_in[0];
    const int*   ei = (const int*)d_in[1];   // int32 (JAX x64 disabled)
    const float* Wq = (const float*)d_in[4];
    const float* bq = (const float*)d_in[5];
    const float* Wk = (const float*)d_in[6];
    const float* bk = (const float*)d_in[7];
    const float* Wv = (const float*)d_in[8];
    const float* bv = (const float*)d_in[9];
    float* out = (float*)d_out;

    int n = in_sizes[0] / 128;
    int E = in_sizes[1] / 2;

    // One-time infra (not device memory; per-call work stays identical)
    static cudaStream_t s2 = nullptr;
    static cudaEvent_t  evFork = nullptr, evJoin = nullptr;
    if (s2 == nullptr) {
        cudaStreamCreateWithFlags(&s2, cudaStreamNonBlocking);
        cudaEventCreateWithFlags(&evFork, cudaEventDisableTiming);
        cudaEventCreateWithFlags(&evJoin, cudaEventDisableTiming);
    }

    // Fork: sort pipeline on side stream (depends only on edge_index)
    cudaEventRecord(evFork, 0);
    cudaStreamWaitEvent(s2, evFork, 0);

    int nb = (n + 1023) / 1024;
    zero_cnt<<<(n + 255) / 256, 256, 0, s2>>>(n);
    hist_kernel<<<(E + 255) / 256, 256, 0, s2>>>(ei, E);
    scan_pass1<<<nb, 256, 0, s2>>>(n);
    scan_pass2<<<1, 256, 0, s2>>>(nb);
    scan_pass3<<<nb, 256, 0, s2>>>(n, E);
    scatter_kernel<<<(E + 255) / 256, 256, 0, s2>>>(ei, E);
    cudaEventRecord(evJoin, s2);

    // Main stream: QKV GEMM (depends only on x, W, b) — overlaps with sort
    const int smem_bytes = (64 * QKSX + 32 * QKSW) * sizeof(float);  // 26624 B
    dim3 gemm_grid((n + 63) / 64, 3);
    qkv_gemm_tc<<<gemm_grid, 256, smem_bytes>>>(x, Wq, bq, Wk, bk, Wv, bv, n);

    // Join, then segmented attention gather (fused normalize)
    cudaStreamWaitEvent(0, evJoin, 0);
    int pairs = (n + 1) / 2;
    gather_kernel<<<(pairs * 32 + 255) / 256, 256>>>(out, n);
}

// round 15
// speedup vs baseline: 1.1654x; 1.1654x over previous
#include <cuda_runtime.h>
#include <cuda_fp16.h>
#include <cstdint>

#define N_MAX   100000
#define E_MAX   800000
#define HD      128
#define NHEADS  8

// Scratch (__device__ globals per allocation rules)
__device__ __half g_Qh[N_MAX * HD];    // Q fp16 (score-path only, like K)
__device__ __half g_KV[N_MAX * 256];   // per node: 32 groups of {K[4],V[4]} fp16
__device__ int    g_cnt[N_MAX];
__device__ int    g_off[N_MAX + 1];
__device__ int    g_pos[N_MAX];
__device__ int    g_srcs[E_MAX];
__device__ int    g_bsum[256];

// ---------------------------------------------------------------------------
// tf32 helpers
// ---------------------------------------------------------------------------
__device__ __forceinline__ float tf32_rna(float x) {
    float r;
    asm("cvt.rna.tf32.f32 %0, %1;" : "=f"(r) : "f"(x));
    return r;
}
__device__ __forceinline__ void mma_tf32(float c[4],
                                         uint32_t a0, uint32_t a1, uint32_t a2, uint32_t a3,
                                         uint32_t b0, uint32_t b1) {
    asm volatile(
        "mma.sync.aligned.m16n8k8.row.col.f32.tf32.tf32.f32 "
        "{%0,%1,%2,%3}, {%4,%5,%6,%7}, {%8,%9}, {%0,%1,%2,%3};"
        : "+f"(c[0]), "+f"(c[1]), "+f"(c[2]), "+f"(c[3])
        : "r"(a0), "r"(a1), "r"(a2), "r"(a3), "r"(b0), "r"(b1));
}

// ---------------------------------------------------------------------------
// QKV GEMM: R12 tile shape (64x128, 8 warps, warp tile 32x32, 4x32 K chunks)
// + double-buffered smem staging with register prefetch: next chunk's global
// loads are issued before computing the current chunk (latency overlapped),
// one __syncthreads per chunk instead of two.
// blockIdx.y: 0 = Q -> g_Qh fp16; 1 = K -> g_KV slot 0; 2 = V -> g_KV slot 4.
// ---------------------------------------------------------------------------
#define QKSX 36
#define QKSW 136
#define CHUNK_FLOATS (64 * QKSX + 32 * QKSW)   // 6656 floats = 26624 B / buffer

__global__ void __launch_bounds__(256)
qkv_gemm_tc(const float* __restrict__ x,
            const float* __restrict__ Wq, const float* __restrict__ bq,
            const float* __restrict__ Wk, const float* __restrict__ bk,
            const float* __restrict__ Wv, const float* __restrict__ bv,
            int n)
{
    const int mode = blockIdx.y;           // 0=Q 1=K 2=V
    const float* W; const float* bias;
    if (mode == 0)      { W = Wq; bias = bq; }
    else if (mode == 1) { W = Wk; bias = bk; }
    else                { W = Wv; bias = bv; }

    extern __shared__ float smemf[];       // 2 buffers of [64][QKSX]+[32][QKSW]

    const int tid   = threadIdx.x;
    const int lane  = tid & 31;
    const int wid   = tid >> 5;
    const int warpM = wid >> 2;
    const int warpN = wid & 3;
    const int g     = lane >> 2;
    const int tg    = lane & 3;
    const int row0  = blockIdx.x * 64;

    // staging coordinates (fixed per thread)
    const int xr  = tid >> 3;              // x row for j=0 (row 0..31); j=1 adds 32
    const int xk4 = (tid & 7) * 4;         // x k offset
    const int wk  = tid >> 5;              // W k row for j=0; j adds 8
    const int wn4 = (tid & 31) * 4;        // W n offset

    float acc[2][4][4];
    #pragma unroll
    for (int mt = 0; mt < 2; mt++)
        #pragma unroll
        for (int nt = 0; nt < 4; nt++)
            #pragma unroll
            for (int i = 0; i < 4; i++) acc[mt][nt][i] = 0.f;

    float4 xv[2], wv[4];

    // ---- register load of one k-chunk ----
    auto load_regs = [&](int kc) {
        #pragma unroll
        for (int j = 0; j < 2; j++) {
            int r  = xr + j * 32;
            int gr = row0 + r;
            xv[j] = make_float4(0.f, 0.f, 0.f, 0.f);
            if (gr < n) xv[j] = *(const float4*)&x[(size_t)gr * 128 + kc + xk4];
        }
        #pragma unroll
        for (int j = 0; j < 4; j++) {
            int kk = wk + j * 8;
            wv[j] = *(const float4*)&W[(size_t)(kc + kk) * 128 + wn4];
        }
    };
    // ---- convert + store regs into buffer b ----
    auto store_smem = [&](int b) {
        float* xs = smemf + b * CHUNK_FLOATS;
        float* ws = xs + 64 * QKSX;
        #pragma unroll
        for (int j = 0; j < 2; j++) {
            float* p = &xs[(xr + j * 32) * QKSX + xk4];
            p[0] = tf32_rna(xv[j].x);
            p[1] = tf32_rna(xv[j].y);
            p[2] = tf32_rna(xv[j].z);
            p[3] = tf32_rna(xv[j].w);
        }
        #pragma unroll
        for (int j = 0; j < 4; j++) {
            float* p = &ws[(wk + j * 8) * QKSW + wn4];
            p[0] = tf32_rna(wv[j].x);
            p[1] = tf32_rna(wv[j].y);
            p[2] = tf32_rna(wv[j].z);
            p[3] = tf32_rna(wv[j].w);
        }
    };
    // ---- compute one k-chunk from buffer b ----
    auto compute = [&](int b) {
        float* xs = smemf + b * CHUNK_FLOATS;
        float* ws = xs + 64 * QKSX;
        #pragma unroll
        for (int k8 = 0; k8 < 4; k8++) {
            const int kb = k8 * 8;
            float af[2][4];
            #pragma unroll
            for (int mt = 0; mt < 2; mt++) {
                int r = warpM * 32 + mt * 16 + g;
                af[mt][0] = xs[r * QKSX + kb + tg];
                af[mt][1] = xs[(r + 8) * QKSX + kb + tg];
                af[mt][2] = xs[r * QKSX + kb + tg + 4];
                af[mt][3] = xs[(r + 8) * QKSX + kb + tg + 4];
            }
            float bfr[4][2];
            #pragma unroll
            for (int nt = 0; nt < 4; nt++) {
                int c = warpN * 32 + nt * 8 + g;
                bfr[nt][0] = ws[(kb + tg) * QKSW + c];
                bfr[nt][1] = ws[(kb + tg + 4) * QKSW + c];
            }
            #pragma unroll
            for (int mt = 0; mt < 2; mt++) {
                #pragma unroll
                for (int nt = 0; nt < 4; nt++) {
                    mma_tf32(acc[mt][nt],
                             __float_as_uint(af[mt][0]), __float_as_uint(af[mt][1]),
                             __float_as_uint(af[mt][2]), __float_as_uint(af[mt][3]),
                             __float_as_uint(bfr[nt][0]), __float_as_uint(bfr[nt][1]));
                }
            }
        }
    };

    // prologue: chunk 0 -> buffer 0
    load_regs(0);
    store_smem(0);
    __syncthreads();

    #pragma unroll
    for (int c = 0; c < 4; c++) {
        if (c < 3) load_regs((c + 1) * 32);   // issue next-chunk global loads
        compute(c & 1);                        // hide load latency under MMAs
        if (c < 3) {
            store_smem((c + 1) & 1);           // regs ready by now
            __syncthreads();
        }
    }

    #pragma unroll
    for (int nt = 0; nt < 4; nt++) {
        int col = warpN * 32 + nt * 8 + tg * 2;
        float b0 = __ldg(&bias[col]);
        float b1 = __ldg(&bias[col + 1]);
        int grp = col >> 2;
        int off = col & 3;
        int kvslot = (mode == 1) ? 0 : 4;
        #pragma unroll
        for (int mt = 0; mt < 2; mt++) {
            #pragma unroll
            for (int half = 0; half < 2; half++) {
                int r = row0 + warpM * 32 + mt * 16 + g + half * 8;
                if (r >= n) continue;
                float o0 = acc[mt][nt][half * 2 + 0] + b0;
                float o1 = acc[mt][nt][half * 2 + 1] + b1;
                __half2 h = __float22half2_rn(make_float2(o0, o1));
                if (mode == 0) {
                    *(__half2*)&g_Qh[(size_t)r * 128 + col] = h;
                } else {
                    size_t hidx = (size_t)r * 256 + grp * 8 + kvslot + off;
                    *(__half2*)&g_KV[hidx] = h;
                }
            }
        }
    }
}

// ---------------------------------------------------------------------------
// Counting sort of edges by dst
// ---------------------------------------------------------------------------
__global__ void zero_cnt(int n)
{
    int i = blockIdx.x * blockDim.x + threadIdx.x;
    if (i < n) g_cnt[i] = 0;
}

__global__ void hist_kernel(const int* __restrict__ ei, int E)
{
    int i = blockIdx.x * blockDim.x + threadIdx.x;
    if (i < E) atomicAdd(&g_cnt[ei[E + i]], 1);
}

__global__ void scan_pass1(int n)
{
    __shared__ int s[256];
    int b   = blockIdx.x;
    int t   = threadIdx.x;
    int idx = b * 1024 + t * 4;
    int sum = 0;
    #pragma unroll
    for (int k = 0; k < 4; k++)
        if (idx + k < n) sum += g_cnt[idx + k];
    s[t] = sum;
    __syncthreads();
    for (int o = 128; o > 0; o >>= 1) {
        if (t < o) s[t] += s[t + o];
        __syncthreads();
    }
    if (t == 0) g_bsum[b] = s[0];
}

__global__ void scan_pass2(int nb)
{
    __shared__ int s[256];
    int t = threadIdx.x;
    s[t] = (t < nb) ? g_bsum[t] : 0;
    __syncthreads();
    #pragma unroll
    for (int o = 1; o < 256; o <<= 1) {
        int add = (t >= o) ? s[t - o] : 0;
        __syncthreads();
        s[t] += add;
        __syncthreads();
    }
    if (t < nb) g_bsum[t] = (t == 0) ? 0 : s[t - 1];
}

__global__ void scan_pass3(int n, int E)
{
    __shared__ int s[256];
    int b   = blockIdx.x;
    int t   = threadIdx.x;
    int idx = b * 1024 + t * 4;
    int v[4];
    int sum = 0;
    #pragma unroll
    for (int k = 0; k < 4; k++) {
        v[k] = (idx + k < n) ? g_cnt[idx + k] : 0;
        sum += v[k];
    }
    s[t] = sum;
    __syncthreads();
    #pragma unroll
    for (int o = 1; o < 256; o <<= 1) {
        int add = (t >= o) ? s[t - o] : 0;
        __syncthreads();
        s[t] += add;
        __syncthreads();
    }
    int base = g_bsum[b] + s[t] - sum;
    #pragma unroll
    for (int k = 0; k < 4; k++) {
        if (idx + k < n) {
            g_off[idx + k] = base;
            g_pos[idx + k] = base;
        }
        base += v[k];
    }
    if (b == 0 && t == 0) g_off[n] = E;
}

__global__ void scatter_kernel(const int* __restrict__ ei, int E)
{
    int i = blockIdx.x * blockDim.x + threadIdx.x;
    if (i >= E) return;
    int src = ei[i];
    int dst = ei[E + i];
    int p = atomicAdd(&g_pos[dst], 1);
    g_srcs[p] = src;
}

// ---------------------------------------------------------------------------
// Segmented gather (exact R12 kernel — confirmed local optimum).
// 1 warp per dst node; MLP-4 clamped chunks; Q fp16 loaded once.
// ---------------------------------------------------------------------------
__device__ __forceinline__ void gather_edge(uint4 pk, float4 q,
                                            float& ax, float& ay, float& az,
                                            float& aw, float& z)
{
    float2 k0 = __half22float2(*(__half2*)&pk.x);
    float2 k1 = __half22float2(*(__half2*)&pk.y);
    float2 v0 = __half22float2(*(__half2*)&pk.z);
    float2 v1 = __half22float2(*(__half2*)&pk.w);

    float dot = k0.x * q.x + k0.y * q.y + k1.x * q.z + k1.y * q.w;
    dot += __shfl_xor_sync(0xffffffffu, dot, 1);
    dot += __shfl_xor_sync(0xffffffffu, dot, 2);
    dot *= 0.25f;
    dot = fminf(fmaxf(dot, -5.0f), 5.0f);
    float score = __expf(dot);

    ax += score * v0.x;
    ay += score * v0.y;
    az += score * v1.x;
    aw += score * v1.y;
    z  += score;
}

__global__ void __launch_bounds__(256)
gather_kernel(float* __restrict__ out, int n)
{
    int node = (blockIdx.x * blockDim.x + threadIdx.x) >> 5;
    int lane = threadIdx.x & 31;
    if (node >= n) return;

    int beg = g_off[node];
    int end = g_off[node + 1];

    // Q fp16 -> fp32 (8 bytes per lane)
    uint2 qp = *(const uint2*)&g_Qh[(size_t)node * 128 + lane * 4];
    float2 q0 = __half22float2(*(__half2*)&qp.x);
    float2 q1 = __half22float2(*(__half2*)&qp.y);
    float4 q = make_float4(q0.x, q0.y, q1.x, q1.y);

    float ax = 0.f, ay = 0.f, az = 0.f, aw = 0.f;
    float z = 0.f;

    int last = end - 1;
    for (int j = beg; j < end; j += 4) {
        int j1 = min(j + 1, last);
        int j2 = min(j + 2, last);
        int j3 = min(j + 3, last);
        int s0 = __ldg(&g_srcs[j]);
        int s1 = __ldg(&g_srcs[j1]);
        int s2 = __ldg(&g_srcs[j2]);
        int s3 = __ldg(&g_srcs[j3]);
        uint4 p0 = *(const uint4*)&g_KV[(size_t)s0 * 256 + lane * 8];
        uint4 p1 = *(const uint4*)&g_KV[(size_t)s1 * 256 + lane * 8];
        uint4 p2 = *(const uint4*)&g_KV[(size_t)s2 * 256 + lane * 8];
        uint4 p3 = *(const uint4*)&g_KV[(size_t)s3 * 256 + lane * 8];
        gather_edge(p0, q, ax, ay, az, aw, z);
        if (j + 1 < end) gather_edge(p1, q, ax, ay, az, aw, z);
        if (j + 2 < end) gather_edge(p2, q, ax, ay, az, aw, z);
        if (j + 3 < end) gather_edge(p3, q, ax, ay, az, aw, z);
    }

    float s = 1.0f / (z + 1e-6f);
    *(float4*)&out[(size_t)node * 128 + lane * 4] =
        make_float4(ax * s, ay * s, az * s, aw * s);
}

// ---------------------------------------------------------------------------
extern "C" void kernel_launch(void* const* d_in, const int* in_sizes, int n_in,
                              void* d_out, int out_size)
{
    const float* x  = (const float*)d_in[0];
    const int*   ei = (const int*)d_in[1];   // int32 (JAX x64 disabled)
    const float* Wq = (const float*)d_in[4];
    const float* bq = (const float*)d_in[5];
    const float* Wk = (const float*)d_in[6];
    const float* bk = (const float*)d_in[7];
    const float* Wv = (const float*)d_in[8];
    const float* bv = (const float*)d_in[9];
    float* out = (float*)d_out;

    int n = in_sizes[0] / 128;
    int E = in_sizes[1] / 2;

    // One-time infra (not device memory; per-call work stays identical)
    static cudaStream_t s2 = nullptr;
    static cudaEvent_t  evFork = nullptr, evJoin = nullptr;
    if (s2 == nullptr) {
        cudaStreamCreateWithFlags(&s2, cudaStreamNonBlocking);
        cudaEventCreateWithFlags(&evFork, cudaEventDisableTiming);
        cudaEventCreateWithFlags(&evJoin, cudaEventDisableTiming);
    }

    // Fork: sort pipeline on side stream (depends only on edge_index)
    cudaEventRecord(evFork, 0);
    cudaStreamWaitEvent(s2, evFork, 0);

    int nb = (n + 1023) / 1024;
    zero_cnt<<<(n + 255) / 256, 256, 0, s2>>>(n);
    hist_kernel<<<(E + 255) / 256, 256, 0, s2>>>(ei, E);
    scan_pass1<<<nb, 256, 0, s2>>>(n);
    scan_pass2<<<1, 256, 0, s2>>>(nb);
    scan_pass3<<<nb, 256, 0, s2>>>(n, E);
    scatter_kernel<<<(E + 255) / 256, 256, 0, s2>>>(ei, E);
    cudaEventRecord(evJoin, s2);

    // Main stream: QKV GEMM (double-buffered staging) — overlaps with sort
    const int smem_bytes = 2 * CHUNK_FLOATS * sizeof(float);   // 53248 B
    cudaFuncSetAttribute(qkv_gemm_tc, cudaFuncAttributeMaxDynamicSharedMemorySize,
                         smem_bytes);
    dim3 gemm_grid((n + 63) / 64, 3);
    qkv_gemm_tc<<<gemm_grid, 256, smem_bytes>>>(x, Wq, bq, Wk, bk, Wv, bv, n);

    // Join, then segmented attention gather (fused normalize)
    cudaStreamWaitEvent(0, evJoin, 0);
    gather_kernel<<<(n * 32 + 255) / 256, 256>>>(out, n);
}

// round 16
// speedup vs baseline: 1.1691x; 1.0032x over previous
#include <cuda_runtime.h>
#include <cuda_fp16.h>
#include <cstdint>

#define N_MAX   100000
#define E_MAX   800000
#define HD      128
#define NHEADS  8

// Scratch (__device__ globals per allocation rules; zero-initialized at load)
__device__ __half g_Qh[N_MAX * HD];    // Q fp16 (score-path only, like K)
__device__ __half g_KV[N_MAX * 256];   // per node: 32 groups of {K[4],V[4]} fp16
__device__ int    g_cnt[N_MAX];        // histogram; self-clearing per launch
__device__ int    g_off[N_MAX + 1];
__device__ int    g_pos[N_MAX];
__device__ int    g_srcs[E_MAX];
__device__ int    g_bsum[256];

// ---------------------------------------------------------------------------
// tf32 helpers
// ---------------------------------------------------------------------------
__device__ __forceinline__ float tf32_rna(float x) {
    float r;
    asm("cvt.rna.tf32.f32 %0, %1;" : "=f"(r) : "f"(x));
    return r;
}
__device__ __forceinline__ void mma_tf32(float c[4],
                                         uint32_t a0, uint32_t a1, uint32_t a2, uint32_t a3,
                                         uint32_t b0, uint32_t b1) {
    asm volatile(
        "mma.sync.aligned.m16n8k8.row.col.f32.tf32.tf32.f32 "
        "{%0,%1,%2,%3}, {%4,%5,%6,%7}, {%8,%9}, {%0,%1,%2,%3};"
        : "+f"(c[0]), "+f"(c[1]), "+f"(c[2]), "+f"(c[3])
        : "r"(a0), "r"(a1), "r"(a2), "r"(a3), "r"(b0), "r"(b1));
}

// ---------------------------------------------------------------------------
// QKV GEMM: 64x128 tile, 8 warps (2 warpM x 4 warpN), warp tile 32x32,
// 4x32 K chunks, double-buffered smem staging with register prefetch
// (R15 config — proven).
// blockIdx.y: 0 = Q -> g_Qh fp16; 1 = K -> g_KV slot 0; 2 = V -> g_KV slot 4.
// ---------------------------------------------------------------------------
#define QKSX 36
#define QKSW 136
#define CHUNK_FLOATS (64 * QKSX + 32 * QKSW)   // 6656 floats = 26624 B / buffer

__global__ void __launch_bounds__(256)
qkv_gemm_tc(const float* __restrict__ x,
            const float* __restrict__ Wq, const float* __restrict__ bq,
            const float* __restrict__ Wk, const float* __restrict__ bk,
            const float* __restrict__ Wv, const float* __restrict__ bv,
            int n)
{
    const int mode = blockIdx.y;           // 0=Q 1=K 2=V
    const float* W; const float* bias;
    if (mode == 0)      { W = Wq; bias = bq; }
    else if (mode == 1) { W = Wk; bias = bk; }
    else                { W = Wv; bias = bv; }

    extern __shared__ float smemf[];       // 2 buffers of [64][QKSX]+[32][QKSW]

    const int tid   = threadIdx.x;
    const int lane  = tid & 31;
    const int wid   = tid >> 5;
    const int warpM = wid >> 2;
    const int warpN = wid & 3;
    const int g     = lane >> 2;
    const int tg    = lane & 3;
    const int row0  = blockIdx.x * 64;

    const int xr  = tid >> 3;
    const int xk4 = (tid & 7) * 4;
    const int wk  = tid >> 5;
    const int wn4 = (tid & 31) * 4;

    float acc[2][4][4];
    #pragma unroll
    for (int mt = 0; mt < 2; mt++)
        #pragma unroll
        for (int nt = 0; nt < 4; nt++)
            #pragma unroll
            for (int i = 0; i < 4; i++) acc[mt][nt][i] = 0.f;

    float4 xv[2], wv[4];

    auto load_regs = [&](int kc) {
        #pragma unroll
        for (int j = 0; j < 2; j++) {
            int r  = xr + j * 32;
            int gr = row0 + r;
            xv[j] = make_float4(0.f, 0.f, 0.f, 0.f);
            if (gr < n) xv[j] = *(const float4*)&x[(size_t)gr * 128 + kc + xk4];
        }
        #pragma unroll
        for (int j = 0; j < 4; j++) {
            int kk = wk + j * 8;
            wv[j] = *(const float4*)&W[(size_t)(kc + kk) * 128 + wn4];
        }
    };
    auto store_smem = [&](int b) {
        float* xs = smemf + b * CHUNK_FLOATS;
        float* ws = xs + 64 * QKSX;
        #pragma unroll
        for (int j = 0; j < 2; j++) {
            float* p = &xs[(xr + j * 32) * QKSX + xk4];
            p[0] = tf32_rna(xv[j].x);
            p[1] = tf32_rna(xv[j].y);
            p[2] = tf32_rna(xv[j].z);
            p[3] = tf32_rna(xv[j].w);
        }
        #pragma unroll
        for (int j = 0; j < 4; j++) {
            float* p = &ws[(wk + j * 8) * QKSW + wn4];
            p[0] = tf32_rna(wv[j].x);
            p[1] = tf32_rna(wv[j].y);
            p[2] = tf32_rna(wv[j].z);
            p[3] = tf32_rna(wv[j].w);
        }
    };
    auto compute = [&](int b) {
        float* xs = smemf + b * CHUNK_FLOATS;
        float* ws = xs + 64 * QKSX;
        #pragma unroll
        for (int k8 = 0; k8 < 4; k8++) {
            const int kb = k8 * 8;
            float af[2][4];
            #pragma unroll
            for (int mt = 0; mt < 2; mt++) {
                int r = warpM * 32 + mt * 16 + g;
                af[mt][0] = xs[r * QKSX + kb + tg];
                af[mt][1] = xs[(r + 8) * QKSX + kb + tg];
                af[mt][2] = xs[r * QKSX + kb + tg + 4];
                af[mt][3] = xs[(r + 8) * QKSX + kb + tg + 4];
            }
            float bfr[4][2];
            #pragma unroll
            for (int nt = 0; nt < 4; nt++) {
                int c = warpN * 32 + nt * 8 + g;
                bfr[nt][0] = ws[(kb + tg) * QKSW + c];
                bfr[nt][1] = ws[(kb + tg + 4) * QKSW + c];
            }
            #pragma unroll
            for (int mt = 0; mt < 2; mt++) {
                #pragma unroll
                for (int nt = 0; nt < 4; nt++) {
                    mma_tf32(acc[mt][nt],
                             __float_as_uint(af[mt][0]), __float_as_uint(af[mt][1]),
                             __float_as_uint(af[mt][2]), __float_as_uint(af[mt][3]),
                             __float_as_uint(bfr[nt][0]), __float_as_uint(bfr[nt][1]));
                }
            }
        }
    };

    load_regs(0);
    store_smem(0);
    __syncthreads();

    #pragma unroll
    for (int c = 0; c < 4; c++) {
        if (c < 3) load_regs((c + 1) * 32);
        compute(c & 1);
        if (c < 3) {
            store_smem((c + 1) & 1);
            __syncthreads();
        }
    }

    #pragma unroll
    for (int nt = 0; nt < 4; nt++) {
        int col = warpN * 32 + nt * 8 + tg * 2;
        float b0 = __ldg(&bias[col]);
        float b1 = __ldg(&bias[col + 1]);
        int grp = col >> 2;
        int off = col & 3;
        int kvslot = (mode == 1) ? 0 : 4;
        #pragma unroll
        for (int mt = 0; mt < 2; mt++) {
            #pragma unroll
            for (int half = 0; half < 2; half++) {
                int r = row0 + warpM * 32 + mt * 16 + g + half * 8;
                if (r >= n) continue;
                float o0 = acc[mt][nt][half * 2 + 0] + b0;
                float o1 = acc[mt][nt][half * 2 + 1] + b1;
                __half2 h = __float22half2_rn(make_float2(o0, o1));
                if (mode == 0) {
                    *(__half2*)&g_Qh[(size_t)r * 128 + col] = h;
                } else {
                    size_t hidx = (size_t)r * 256 + grp * 8 + kvslot + off;
                    *(__half2*)&g_KV[hidx] = h;
                }
            }
        }
    }
}

// ---------------------------------------------------------------------------
// Counting sort of edges by dst.
// g_cnt is self-clearing: zero-initialized at module load; scan_pass3 writes
// 0 back to every bin it reads, so each launch (and graph replay) starts from
// zeros without a separate zero_cnt kernel.
// ---------------------------------------------------------------------------
__global__ void hist_kernel(const int* __restrict__ ei, int E)
{
    int i = blockIdx.x * blockDim.x + threadIdx.x;
    if (i < E) atomicAdd(&g_cnt[ei[E + i]], 1);
}

__global__ void scan_pass1(int n)
{
    __shared__ int s[256];
    int b   = blockIdx.x;
    int t   = threadIdx.x;
    int idx = b * 1024 + t * 4;
    int sum = 0;
    #pragma unroll
    for (int k = 0; k < 4; k++)
        if (idx + k < n) sum += g_cnt[idx + k];
    s[t] = sum;
    __syncthreads();
    for (int o = 128; o > 0; o >>= 1) {
        if (t < o) s[t] += s[t + o];
        __syncthreads();
    }
    if (t == 0) g_bsum[b] = s[0];
}

__global__ void scan_pass2(int nb)
{
    __shared__ int s[256];
    int t = threadIdx.x;
    s[t] = (t < nb) ? g_bsum[t] : 0;
    __syncthreads();
    #pragma unroll
    for (int o = 1; o < 256; o <<= 1) {
        int add = (t >= o) ? s[t - o] : 0;
        __syncthreads();
        s[t] += add;
        __syncthreads();
    }
    if (t < nb) g_bsum[t] = (t == 0) ? 0 : s[t - 1];
}

__global__ void scan_pass3(int n, int E)
{
    __shared__ int s[256];
    int b   = blockIdx.x;
    int t   = threadIdx.x;
    int idx = b * 1024 + t * 4;
    int v[4];
    int sum = 0;
    #pragma unroll
    for (int k = 0; k < 4; k++) {
        v[k] = (idx + k < n) ? g_cnt[idx + k] : 0;
        sum += v[k];
    }
    // self-clear for next launch / graph replay
    #pragma unroll
    for (int k = 0; k < 4; k++)
        if (idx + k < n) g_cnt[idx + k] = 0;
    s[t] = sum;
    __syncthreads();
    #pragma unroll
    for (int o = 1; o < 256; o <<= 1) {
        int add = (t >= o) ? s[t - o] : 0;
        __syncthreads();
        s[t] += add;
        __syncthreads();
    }
    int base = g_bsum[b] + s[t] - sum;
    #pragma unroll
    for (int k = 0; k < 4; k++) {
        if (idx + k < n) {
            g_off[idx + k] = base;
            g_pos[idx + k] = base;
        }
        base += v[k];
    }
    if (b == 0 && t == 0) g_off[n] = E;
}

__global__ void scatter_kernel(const int* __restrict__ ei, int E)
{
    int i = blockIdx.x * blockDim.x + threadIdx.x;
    if (i >= E) return;
    int src = ei[i];
    int dst = ei[E + i];
    int p = atomicAdd(&g_pos[dst], 1);
    g_srcs[p] = src;
}

// ---------------------------------------------------------------------------
// Segmented gather (R12 kernel — confirmed local optimum).
// 1 warp per dst node; MLP-4 clamped chunks; Q fp16 loaded once.
// ---------------------------------------------------------------------------
__device__ __forceinline__ void gather_edge(uint4 pk, float4 q,
                                            float& ax, float& ay, float& az,
                                            float& aw, float& z)
{
    float2 k0 = __half22float2(*(__half2*)&pk.x);
    float2 k1 = __half22float2(*(__half2*)&pk.y);
    float2 v0 = __half22float2(*(__half2*)&pk.z);
    float2 v1 = __half22float2(*(__half2*)&pk.w);

    float dot = k0.x * q.x + k0.y * q.y + k1.x * q.z + k1.y * q.w;
    dot += __shfl_xor_sync(0xffffffffu, dot, 1);
    dot += __shfl_xor_sync(0xffffffffu, dot, 2);
    dot *= 0.25f;
    dot = fminf(fmaxf(dot, -5.0f), 5.0f);
    float score = __expf(dot);

    ax += score * v0.x;
    ay += score * v0.y;
    az += score * v1.x;
    aw += score * v1.y;
    z  += score;
}

__global__ void __launch_bounds__(256)
gather_kernel(float* __restrict__ out, int n)
{
    int node = (blockIdx.x * blockDim.x + threadIdx.x) >> 5;
    int lane = threadIdx.x & 31;
    if (node >= n) return;

    int beg = g_off[node];
    int end = g_off[node + 1];

    uint2 qp = *(const uint2*)&g_Qh[(size_t)node * 128 + lane * 4];
    float2 q0 = __half22float2(*(__half2*)&qp.x);
    float2 q1 = __half22float2(*(__half2*)&qp.y);
    float4 q = make_float4(q0.x, q0.y, q1.x, q1.y);

    float ax = 0.f, ay = 0.f, az = 0.f, aw = 0.f;
    float z = 0.f;

    int last = end - 1;
    for (int j = beg; j < end; j += 4) {
        int j1 = min(j + 1, last);
        int j2 = min(j + 2, last);
        int j3 = min(j + 3, last);
        int s0 = __ldg(&g_srcs[j]);
        int s1 = __ldg(&g_srcs[j1]);
        int s2 = __ldg(&g_srcs[j2]);
        int s3 = __ldg(&g_srcs[j3]);
        uint4 p0 = *(const uint4*)&g_KV[(size_t)s0 * 256 + lane * 8];
        uint4 p1 = *(const uint4*)&g_KV[(size_t)s1 * 256 + lane * 8];
        uint4 p2 = *(const uint4*)&g_KV[(size_t)s2 * 256 + lane * 8];
        uint4 p3 = *(const uint4*)&g_KV[(size_t)s3 * 256 + lane * 8];
        gather_edge(p0, q, ax, ay, az, aw, z);
        if (j + 1 < end) gather_edge(p1, q, ax, ay, az, aw, z);
        if (j + 2 < end) gather_edge(p2, q, ax, ay, az, aw, z);
        if (j + 3 < end) gather_edge(p3, q, ax, ay, az, aw, z);
    }

    float s = 1.0f / (z + 1e-6f);
    *(float4*)&out[(size_t)node * 128 + lane * 4] =
        make_float4(ax * s, ay * s, az * s, aw * s);
}

// ---------------------------------------------------------------------------
extern "C" void kernel_launch(void* const* d_in, const int* in_sizes, int n_in,
                              void* d_out, int out_size)
{
    const float* x  = (const float*)d_in[0];
    const int*   ei = (const int*)d_in[1];   // int32 (JAX x64 disabled)
    const float* Wq = (const float*)d_in[4];
    const float* bq = (const float*)d_in[5];
    const float* Wk = (const float*)d_in[6];
    const float* bk = (const float*)d_in[7];
    const float* Wv = (const float*)d_in[8];
    const float* bv = (const float*)d_in[9];
    float* out = (float*)d_out;

    int n = in_sizes[0] / 128;
    int E = in_sizes[1] / 2;

    // One-time infra (not device memory; per-call work stays identical).
    // Side stream at LOWEST priority: sort blocks fill GEMM's idle slots
    // instead of contending head-on for SMs/L2.
    static cudaStream_t s2 = nullptr;
    static cudaEvent_t  evFork = nullptr, evJoin = nullptr;
    if (s2 == nullptr) {
        int loPri = 0, hiPri = 0;
        cudaDeviceGetStreamPriorityRange(&loPri, &hiPri);  // loPri = least
        cudaStreamCreateWithPriority(&s2, cudaStreamNonBlocking, loPri);
        cudaEventCreateWithFlags(&evFork, cudaEventDisableTiming);
        cudaEventCreateWithFlags(&evJoin, cudaEventDisableTiming);
    }

    // Fork: sort pipeline on low-priority side stream (reads only edge_index)
    cudaEventRecord(evFork, 0);
    cudaStreamWaitEvent(s2, evFork, 0);

    int nb = (n + 1023) / 1024;
    hist_kernel<<<(E + 255) / 256, 256, 0, s2>>>(ei, E);
    scan_pass1<<<nb, 256, 0, s2>>>(n);
    scan_pass2<<<1, 256, 0, s2>>>(nb);
    scan_pass3<<<nb, 256, 0, s2>>>(n, E);
    scatter_kernel<<<(E + 255) / 256, 256, 0, s2>>>(ei, E);
    cudaEventRecord(evJoin, s2);

    // Main stream: QKV GEMM (double-buffered staging) — overlaps with sort
    const int smem_bytes = 2 * CHUNK_FLOATS * sizeof(float);   // 53248 B
    cudaFuncSetAttribute(qkv_gemm_tc, cudaFuncAttributeMaxDynamicSharedMemorySize,
                         smem_bytes);
    dim3 gemm_grid((n + 63) / 64, 3);
    qkv_gemm_tc<<<gemm_grid, 256, smem_bytes>>>(x, Wq, bq, Wk, bk, Wv, bv, n);

    // Join, then segmented attention gather (fused normalize)
    cudaStreamWaitEvent(0, evJoin, 0);
    gather_kernel<<<(n * 32 + 255) / 256, 256>>>(out, n);
}